// round 7
// baseline (speedup 1.0000x reference)
#include <cuda_runtime.h>
#include <cuda_bf16.h>

// SimOTA dynamic label assignment — single persistent kernel, 3 phases,
// phase 2 = proven one-warp-per-GT body from the passing round-3 kernel.
// Inputs: 0 pred_scores (A*80) f32 | 1 pred_bboxes (A*4) f32 |
//         2 anchor_points (A*2) f32 | 3 gt_labels (G) i32 | 4 gt_bboxes (G*4) f32
// Output f32: labels (A) | bboxes (A*4) | scores (A*81)

#define A_MAX 33600
#define TOPK 10
#define NCLS 80
#define GRIDW 20
#define NCELLS (GRIDW * GRIDW)
#define INV_CELL (1.0f / 64.0f)
#define CAP 224
#define NBLK 148
#define NTHR 512

__device__ float  g_total_neg[A_MAX];
__device__ float  g_area_p[A_MAX];
__device__ int    g_assigned[A_MAX];
__device__ int    g_cnt[NCELLS];        // zero at load; phase 3 re-zeroes each call
__device__ int    g_sa_idx[NCELLS * CAP];
__device__ float2 g_sa_pt[NCELLS * CAP];

// grid barrier (monotone generation counter -> graph-replay safe; count
// returns to 0 after every barrier, so state is identical at each replay)
__device__ unsigned g_bar_count;
__device__ volatile unsigned g_bar_gen;

__device__ __forceinline__ void grid_barrier() {
    __syncthreads();
    if (threadIdx.x == 0) {
        unsigned gen = g_bar_gen;
        __threadfence();
        if (atomicAdd(&g_bar_count, 1u) == (unsigned)(gridDim.x - 1)) {
            g_bar_count = 0u;
            __threadfence();
            g_bar_gen = gen + 1u;
        } else {
            while (g_bar_gen == gen) __nanosleep(64);
        }
        __threadfence();
    }
    __syncthreads();
}

__global__ __launch_bounds__(NTHR, 1)
void simota_kernel(const float* __restrict__ scores,
                   const float* __restrict__ pbox,
                   const float* __restrict__ apts,
                   const int*   __restrict__ glab,
                   const float* __restrict__ gbox,
                   float* __restrict__ out, int A, int G) {
    const int tid  = blockIdx.x * NTHR + threadIdx.x;
    const int nthr = gridDim.x * NTHR;

    // ======================= Phase 1 =======================
    // per-anchor total_neg (sequential class order — bit-exact), area_p,
    // assigned=-1, capacity-binned insert; plus zero-fill of scores region.
    for (int a = tid; a < A; a += nthr) {
        const float4* row = reinterpret_cast<const float4*>(scores + (size_t)a * NCLS);
        float tn = 0.f;
        #pragma unroll 5
        for (int q = 0; q < NCLS / 4; q++) {
            float4 v = row[q];
            float s;
            s = v.x; tn = __fadd_rn(tn, __fadd_rn(fmaxf(s, 0.f), log1pf(expf(-fabsf(s)))));
            s = v.y; tn = __fadd_rn(tn, __fadd_rn(fmaxf(s, 0.f), log1pf(expf(-fabsf(s)))));
            s = v.z; tn = __fadd_rn(tn, __fadd_rn(fmaxf(s, 0.f), log1pf(expf(-fabsf(s)))));
            s = v.w; tn = __fadd_rn(tn, __fadd_rn(fmaxf(s, 0.f), log1pf(expf(-fabsf(s)))));
        }
        g_total_neg[a] = tn;

        float4 pb = reinterpret_cast<const float4*>(pbox)[a];
        g_area_p[a] = __fmul_rn(__fsub_rn(pb.z, pb.x), __fsub_rn(pb.w, pb.y));
        g_assigned[a] = -1;

        float2 p = reinterpret_cast<const float2*>(apts)[a];
        int cx = min(GRIDW - 1, max(0, (int)(p.x * INV_CELL)));
        int cy = min(GRIDW - 1, max(0, (int)(p.y * INV_CELL)));
        int cell = cy * GRIDW + cx;
        int slot = atomicAdd(&g_cnt[cell], 1);
        if (slot < CAP) {
            g_sa_idx[cell * CAP + slot] = a;
            g_sa_pt[cell * CAP + slot] = p;
        }
    }
    {
        int n4 = (A * (NCLS + 1)) >> 2;
        float4* dst = reinterpret_cast<float4*>(out + (size_t)5 * A);
        for (int i = tid; i < n4; i += nthr)
            dst[i] = make_float4(0.f, 0.f, 0.f, 0.f);
        for (int t = n4 * 4 + tid; t < A * (NCLS + 1); t += nthr)
            out[(size_t)5 * A + t] = 0.f;
    }

    grid_barrier();

    // ======================= Phase 2 =======================
    // One warp per GT (proven body). GT g -> block g%148, warp g/148, so
    // working warps spread across all SMs. No shared mem, no intra-phase sync.
    {
        const int wid  = threadIdx.x >> 5;
        const int lane = threadIdx.x & 31;
        int g = blockIdx.x + gridDim.x * wid;
        if (g < G) {
            float4 gb4 = reinterpret_cast<const float4*>(gbox)[g];
            float x1 = gb4.x, y1 = gb4.y, x2 = gb4.z, y2 = gb4.w;
            int label = glab[g];
            float areag = __fmul_rn(__fsub_rn(x2, x1), __fsub_rn(y2, y1));

            int cx0 = max(0, min(GRIDW - 1, (int)(x1 * INV_CELL)));
            int cx1 = max(0, min(GRIDW - 1, (int)(x2 * INV_CELL)));
            int cy0 = max(0, min(GRIDW - 1, (int)(y1 * INV_CELL)));
            int cy1 = max(0, min(GRIDW - 1, (int)(y2 * INV_CELL)));

            unsigned long long loc[TOPK];
            #pragma unroll
            for (int k = 0; k < TOPK; k++) loc[k] = 0xFFFFFFFFFFFFFFFFULL;
            int cnt = 0, icnt = 0;

            for (int cy = cy0; cy <= cy1; cy++) {
                for (int cx = cx0; cx <= cx1; cx++) {
                    int c = cy * GRIDW + cx;
                    int n = min(g_cnt[c], CAP);
                    int base = c * CAP;
                    for (int i = lane; i < n; i += 32) {
                        float2 p = g_sa_pt[base + i];
                        if (p.x >= x1 && p.x <= x2 && p.y >= y1 && p.y <= y2) {
                            icnt++;
                            int a = g_sa_idx[base + i];
                            float4 pb = reinterpret_cast<const float4*>(pbox)[a];
                            float ltx = fmaxf(pb.x, x1), lty = fmaxf(pb.y, y1);
                            float rbx = fminf(pb.z, x2), rby = fminf(pb.w, y2);
                            float w = fmaxf(__fsub_rn(rbx, ltx), 0.f);
                            float h = fmaxf(__fsub_rn(rby, lty), 0.f);
                            float ov = __fmul_rn(w, h);
                            cnt += (ov > 0.f);
                            float denom = __fadd_rn(__fsub_rn(__fadd_rn(g_area_p[a], areag), ov), 1e-6f);
                            float iou = __fdiv_rn(ov, denom);
                            float ic = -logf(fmaxf(iou, 1e-7f));
                            float s = scores[(size_t)a * NCLS + label];
                            float L = log1pf(expf(-fabsf(s)));
                            float spp = __fadd_rn(fmaxf(-s, 0.f), L);
                            float spn = __fadd_rn(fmaxf(s, 0.f), L);
                            float cls = __fadd_rn(g_total_neg[a], __fsub_rn(spp, spn));
                            float cost = __fadd_rn(cls, __fmul_rn(3.0f, ic));
                            unsigned long long key =
                                (((unsigned long long)__float_as_uint(cost)) << 32) | (unsigned)a;
                            if (key < loc[TOPK - 1]) {
                                loc[TOPK - 1] = key;
                                #pragma unroll
                                for (int k = TOPK - 1; k > 0; k--) {
                                    unsigned long long lo = loc[k - 1], hi = loc[k];
                                    if (hi < lo) { loc[k] = lo; loc[k - 1] = hi; }
                                }
                            }
                        }
                    }
                }
            }

            #pragma unroll
            for (int o = 16; o; o >>= 1) {
                cnt  += __shfl_xor_sync(0xffffffffu, cnt, o);
                icnt += __shfl_xor_sync(0xffffffffu, icnt, o);
            }
            int dynk = min(max(cnt, 1), TOPK);

            // warp-merge: lane r ends holding the rank-r winner's anchor index
            unsigned win = 0xFFFFFFFFu;
            int ptr = 0;
            for (int r = 0; r < TOPK; r++) {
                unsigned long long v = 0xFFFFFFFFFFFFFFFFULL;
                #pragma unroll
                for (int k = 0; k < TOPK; k++) if (ptr == k) v = loc[k];
                unsigned long long m = v;
                #pragma unroll
                for (int o = 16; o; o >>= 1) {
                    unsigned long long other = __shfl_xor_sync(0xffffffffu, m, o);
                    if (other < m) m = other;
                }
                if (v == m) ptr++;
                if (lane == r) win = (unsigned)(m & 0xFFFFFFFFULL);
            }

            if (icnt == 0) {
                // all anchors outside: uniform 1e10 costs -> indices 0..9;
                // dynk==1 -> only anchor 0 receives this GT.
                if (lane == 0) atomicMax(&g_assigned[0], g);
            } else if (lane < dynk && win < (unsigned)A) {
                atomicMax(&g_assigned[win], g);
            }
        }
    }

    grid_barrier();

    // ======================= Phase 3 =======================
    for (int a = tid; a < A; a += nthr) {
        int g = g_assigned[a];
        bool pos = g >= 0;
        int gs = pos ? g : 0;
        float4 gb = reinterpret_cast<const float4*>(gbox)[gs];
        float4 pb = reinterpret_cast<const float4*>(pbox)[a];
        float ltx = fmaxf(pb.x, gb.x), lty = fmaxf(pb.y, gb.y);
        float rbx = fminf(pb.z, gb.z), rby = fminf(pb.w, gb.w);
        float w = fmaxf(__fsub_rn(rbx, ltx), 0.f);
        float h = fmaxf(__fsub_rn(rby, lty), 0.f);
        float ov = __fmul_rn(w, h);
        float areag = __fmul_rn(__fsub_rn(gb.z, gb.x), __fsub_rn(gb.w, gb.y));
        float denom = __fadd_rn(__fsub_rn(__fadd_rn(g_area_p[a], areag), ov), 1e-6f);
        float iou = __fdiv_rn(ov, denom);

        int lab = pos ? glab[gs] : NCLS;
        out[a] = (float)lab;
        float4 ob = pos ? gb : make_float4(0.f, 0.f, 0.f, 0.f);
        reinterpret_cast<float4*>(out + A)[a] = ob;
        out[(size_t)5 * A + (size_t)a * (NCLS + 1) + lab] = pos ? iou : 0.f;
    }
    // reset bin counters for the next graph replay
    for (int c = tid; c < NCELLS; c += nthr) g_cnt[c] = 0;
}

extern "C" void kernel_launch(void* const* d_in, const int* in_sizes, int n_in,
                              void* d_out, int out_size) {
    const float* scores = (const float*)d_in[0];
    const float* pbox   = (const float*)d_in[1];
    const float* apts   = (const float*)d_in[2];
    const int*   glab   = (const int*)d_in[3];
    const float* gbox   = (const float*)d_in[4];
    float* out = (float*)d_out;

    int A = in_sizes[2] / 2;
    int G = in_sizes[3];

    simota_kernel<<<NBLK, NTHR>>>(scores, pbox, apts, glab, gbox, out, A, G);
}

// round 8
// speedup vs baseline: 1.9910x; 1.9910x over previous
#include <cuda_runtime.h>
#include <cuda_bf16.h>

// SimOTA dynamic label assignment — single persistent kernel, 3 phases.
// Phase 1: all-SM streaming precompute + packed candidate bins + zero-fill.
// Phase 2: 8 warps per GT, two-stage proven ptr-merge top-10, fused scatter.
// Phase 3: finalize outputs, reset bin counters.
// Inputs: 0 pred_scores (A*80) f32 | 1 pred_bboxes (A*4) f32 |
//         2 anchor_points (A*2) f32 | 3 gt_labels (G) i32 | 4 gt_bboxes (G*4) f32
// Output f32: labels (A) | bboxes (A*4) | scores (A*81)

#define A_MAX 33600
#define TOPK 10
#define NCLS 80
#define GRIDW 20
#define NCELLS (GRIDW * GRIDW)
#define INV_CELL (1.0f / 64.0f)
#define CAP 224
#define NBLK 296          // 2 per SM, co-resident via __launch_bounds__(512,2)
#define NTHR 512
#define SENT 0xFFFFFFFFFFFFFFFFULL

__device__ float  g_area_p[A_MAX];
__device__ int    g_assigned[A_MAX];
__device__ int    g_cnt[NCELLS];          // zero at load; phase 3 re-zeroes
__device__ float4 g_candA[NCELLS * CAP];  // px, py, pbx1, pby1
__device__ float4 g_candB[NCELLS * CAP];  // pbx2, pby2, total_neg, idx(bits)

// grid barrier (monotone generation counter -> graph-replay safe)
__device__ unsigned g_bar_count;
__device__ volatile unsigned g_bar_gen;

__device__ __forceinline__ void grid_barrier() {
    __syncthreads();
    if (threadIdx.x == 0) {
        unsigned gen = g_bar_gen;
        __threadfence();
        if (atomicAdd(&g_bar_count, 1u) == (unsigned)(gridDim.x - 1)) {
            g_bar_count = 0u;
            __threadfence();
            g_bar_gen = gen + 1u;
        } else {
            while (g_bar_gen == gen) __nanosleep(64);
        }
        __threadfence();
    }
    __syncthreads();
}

__global__ __launch_bounds__(NTHR, 2)
void simota_kernel(const float* __restrict__ scores,
                   const float* __restrict__ pbox,
                   const float* __restrict__ apts,
                   const int*   __restrict__ glab,
                   const float* __restrict__ gbox,
                   float* __restrict__ out, int A, int G) {
    const int tid  = blockIdx.x * NTHR + threadIdx.x;
    const int nthr = gridDim.x * NTHR;

    // ======================= Phase 1 =======================
    // Block b owns anchors [b*chunk, b*chunk+chunk) -> every SM streams DRAM.
    {
        int chunk = (A + gridDim.x - 1) / gridDim.x;    // 114 for A=33600
        int a = blockIdx.x * chunk + threadIdx.x;
        if (threadIdx.x < chunk && a < A) {
            const float4* row = reinterpret_cast<const float4*>(scores + (size_t)a * NCLS);
            float tn = 0.f;
            #pragma unroll 5
            for (int q = 0; q < NCLS / 4; q++) {
                float4 v = row[q];
                float s;
                s = v.x; tn = __fadd_rn(tn, __fadd_rn(fmaxf(s, 0.f), log1pf(expf(-fabsf(s)))));
                s = v.y; tn = __fadd_rn(tn, __fadd_rn(fmaxf(s, 0.f), log1pf(expf(-fabsf(s)))));
                s = v.z; tn = __fadd_rn(tn, __fadd_rn(fmaxf(s, 0.f), log1pf(expf(-fabsf(s)))));
                s = v.w; tn = __fadd_rn(tn, __fadd_rn(fmaxf(s, 0.f), log1pf(expf(-fabsf(s)))));
            }
            float4 pb = reinterpret_cast<const float4*>(pbox)[a];
            g_area_p[a] = __fmul_rn(__fsub_rn(pb.z, pb.x), __fsub_rn(pb.w, pb.y));
            g_assigned[a] = -1;

            float2 p = reinterpret_cast<const float2*>(apts)[a];
            int cx = min(GRIDW - 1, max(0, (int)(p.x * INV_CELL)));
            int cy = min(GRIDW - 1, max(0, (int)(p.y * INV_CELL)));
            int cell = cy * GRIDW + cx;
            int slot = atomicAdd(&g_cnt[cell], 1);
            if (slot < CAP) {
                g_candA[cell * CAP + slot] = make_float4(p.x, p.y, pb.x, pb.y);
                g_candB[cell * CAP + slot] = make_float4(pb.z, pb.w, tn, __int_as_float(a));
            }
        }
        // zero-fill scores region (all threads)
        int n4 = (A * (NCLS + 1)) >> 2;
        float4* dst = reinterpret_cast<float4*>(out + (size_t)5 * A);
        for (int i = tid; i < n4; i += nthr)
            dst[i] = make_float4(0.f, 0.f, 0.f, 0.f);
        for (int t = n4 * 4 + tid; t < A * (NCLS + 1); t += nthr)
            out[(size_t)5 * A + t] = 0.f;
    }

    grid_barrier();

    // ======================= Phase 2 =======================
    // 8 warps per GT; block holds 2 GT groups. Stride 256 >= CAP means
    // each (cell, candidate) is visited by exactly one lane of one warp.
    {
        const int wid   = threadIdx.x >> 5;
        const int lane  = threadIdx.x & 31;
        const int halfg = wid >> 3;          // GT group within block
        const int wg    = wid & 7;           // warp within group
        int g = blockIdx.x * 2 + halfg;

        __shared__ unsigned long long s_top[2][8 * TOPK];
        __shared__ int s_cnt[2][8], s_icnt[2][8];

        if (g < G) {
            float4 gb4 = reinterpret_cast<const float4*>(gbox)[g];
            float x1 = gb4.x, y1 = gb4.y, x2 = gb4.z, y2 = gb4.w;
            int label = glab[g];
            float areag = __fmul_rn(__fsub_rn(x2, x1), __fsub_rn(y2, y1));

            int cx0 = max(0, min(GRIDW - 1, (int)(x1 * INV_CELL)));
            int cx1 = max(0, min(GRIDW - 1, (int)(x2 * INV_CELL)));
            int cy0 = max(0, min(GRIDW - 1, (int)(y1 * INV_CELL)));
            int cy1 = max(0, min(GRIDW - 1, (int)(y2 * INV_CELL)));

            unsigned long long loc[TOPK];
            #pragma unroll
            for (int k = 0; k < TOPK; k++) loc[k] = SENT;
            int cnt = 0, icnt = 0;

            for (int cy = cy0; cy <= cy1; cy++) {
                for (int cx = cx0; cx <= cx1; cx++) {
                    int c = cy * GRIDW + cx;
                    int n = min(g_cnt[c], CAP);
                    int i = (wg << 5) + lane;
                    if (i < n) {
                        int base = c * CAP + i;
                        float4 rA = g_candA[base];   // px,py,pbx1,pby1
                        float4 rB = g_candB[base];   // pbx2,pby2,tn,idx
                        if (rA.x >= x1 && rA.x <= x2 && rA.y >= y1 && rA.y <= y2) {
                            icnt++;
                            int a = __float_as_int(rB.w);
                            float s = scores[(size_t)a * NCLS + label];
                            float areap = __fmul_rn(__fsub_rn(rB.x, rA.z),
                                                    __fsub_rn(rB.y, rA.w));
                            float ltx = fmaxf(rA.z, x1), lty = fmaxf(rA.w, y1);
                            float rbx = fminf(rB.x, x2), rby = fminf(rB.y, y2);
                            float w = fmaxf(__fsub_rn(rbx, ltx), 0.f);
                            float h = fmaxf(__fsub_rn(rby, lty), 0.f);
                            float ov = __fmul_rn(w, h);
                            cnt += (ov > 0.f);
                            float denom = __fadd_rn(__fsub_rn(__fadd_rn(areap, areag), ov), 1e-6f);
                            float iou = __fdiv_rn(ov, denom);
                            float ic = -logf(fmaxf(iou, 1e-7f));
                            float L = log1pf(expf(-fabsf(s)));
                            float spp = __fadd_rn(fmaxf(-s, 0.f), L);
                            float spn = __fadd_rn(fmaxf(s, 0.f), L);
                            float cls = __fadd_rn(rB.z, __fsub_rn(spp, spn));
                            float cost = __fadd_rn(cls, __fmul_rn(3.0f, ic));
                            unsigned long long key =
                                (((unsigned long long)__float_as_uint(cost)) << 32) | (unsigned)a;
                            if (key < loc[TOPK - 1]) {
                                loc[TOPK - 1] = key;
                                #pragma unroll
                                for (int k = TOPK - 1; k > 0; k--) {
                                    unsigned long long lo = loc[k - 1], hi = loc[k];
                                    if (hi < lo) { loc[k] = lo; loc[k - 1] = hi; }
                                }
                            }
                        }
                    }
                }
            }

            #pragma unroll
            for (int o = 16; o; o >>= 1) {
                cnt  += __shfl_xor_sync(0xffffffffu, cnt, o);
                icnt += __shfl_xor_sync(0xffffffffu, icnt, o);
            }

            // stage 1: proven per-warp ptr-merge; lane r keeps full rank-r key
            unsigned long long kwin = SENT;
            int ptr = 0;
            for (int r = 0; r < TOPK; r++) {
                unsigned long long v = SENT;
                #pragma unroll
                for (int k = 0; k < TOPK; k++) if (ptr == k) v = loc[k];
                unsigned long long m = v;
                #pragma unroll
                for (int o = 16; o; o >>= 1) {
                    unsigned long long other = __shfl_xor_sync(0xffffffffu, m, o);
                    if (other < m) m = other;
                }
                if (v == m) ptr++;
                if (lane == r) kwin = m;
            }
            if (lane == 0) { s_cnt[halfg][wg] = cnt; s_icnt[halfg][wg] = icnt; }
            if (lane < TOPK) s_top[halfg][wg * TOPK + lane] = kwin;
        }
        __syncthreads();

        // stage 2: warp 0 of each group merges 8 sorted lists (same primitive)
        if (g < G && wg == 0) {
            unsigned long long l[TOPK];
            #pragma unroll
            for (int k = 0; k < TOPK; k++)
                l[k] = (lane < 8) ? s_top[halfg][lane * TOPK + k] : SENT;
            int cnt  = (lane < 8) ? s_cnt[halfg][lane]  : 0;
            int icnt = (lane < 8) ? s_icnt[halfg][lane] : 0;
            #pragma unroll
            for (int o = 16; o; o >>= 1) {
                cnt  += __shfl_xor_sync(0xffffffffu, cnt, o);
                icnt += __shfl_xor_sync(0xffffffffu, icnt, o);
            }
            int dynk = min(max(cnt, 1), TOPK);

            unsigned win = 0xFFFFFFFFu;
            int ptr = 0;
            for (int r = 0; r < TOPK; r++) {
                unsigned long long v = SENT;
                #pragma unroll
                for (int k = 0; k < TOPK; k++) if (ptr == k) v = l[k];
                unsigned long long m = v;
                #pragma unroll
                for (int o = 16; o; o >>= 1) {
                    unsigned long long other = __shfl_xor_sync(0xffffffffu, m, o);
                    if (other < m) m = other;
                }
                if (v == m) ptr++;
                if (lane == r) win = (unsigned)(m & 0xFFFFFFFFULL);
            }

            if (icnt == 0) {
                // all anchors outside: uniform 1e10 costs -> indices 0..9;
                // dynk==1 -> only anchor 0 receives this GT.
                if (lane == 0) atomicMax(&g_assigned[0], g);
            } else if (lane < dynk && win < (unsigned)A) {
                atomicMax(&g_assigned[win], g);
            }
        }
    }

    grid_barrier();

    // ======================= Phase 3 =======================
    for (int a = tid; a < A; a += nthr) {
        int g = g_assigned[a];
        bool pos = g >= 0;
        int gs = pos ? g : 0;
        float4 gb = reinterpret_cast<const float4*>(gbox)[gs];
        float4 pb = reinterpret_cast<const float4*>(pbox)[a];
        float ltx = fmaxf(pb.x, gb.x), lty = fmaxf(pb.y, gb.y);
        float rbx = fminf(pb.z, gb.z), rby = fminf(pb.w, gb.w);
        float w = fmaxf(__fsub_rn(rbx, ltx), 0.f);
        float h = fmaxf(__fsub_rn(rby, lty), 0.f);
        float ov = __fmul_rn(w, h);
        float areag = __fmul_rn(__fsub_rn(gb.z, gb.x), __fsub_rn(gb.w, gb.y));
        float denom = __fadd_rn(__fsub_rn(__fadd_rn(g_area_p[a], areag), ov), 1e-6f);
        float iou = __fdiv_rn(ov, denom);

        int lab = pos ? glab[gs] : NCLS;
        out[a] = (float)lab;
        float4 ob = pos ? gb : make_float4(0.f, 0.f, 0.f, 0.f);
        reinterpret_cast<float4*>(out + A)[a] = ob;
        out[(size_t)5 * A + (size_t)a * (NCLS + 1) + lab] = pos ? iou : 0.f;
    }
    // reset bin counters for the next graph replay
    for (int c = tid; c < NCELLS; c += nthr) g_cnt[c] = 0;
}

extern "C" void kernel_launch(void* const* d_in, const int* in_sizes, int n_in,
                              void* d_out, int out_size) {
    const float* scores = (const float*)d_in[0];
    const float* pbox   = (const float*)d_in[1];
    const float* apts   = (const float*)d_in[2];
    const int*   glab   = (const int*)d_in[3];
    const float* gbox   = (const float*)d_in[4];
    float* out = (float*)d_out;

    int A = in_sizes[2] / 2;
    int G = in_sizes[3];

    simota_kernel<<<NBLK, NTHR>>>(scores, pbox, apts, glab, gbox, out, A, G);
}